// round 14
// baseline (speedup 1.0000x reference)
#include <cuda_runtime.h>
#include <math.h>

#define Bsz 256
#define Xd  256
#define Hd  512
#define Rd  128
#define Md  128
#define Td  256
#define XHD 768      // X+H
#define CATD 896     // X+H+R
#define NPRE 2176    // R+4H columns of W_full
#define NG1 640      // R+H
#define ODIM 640
#define NBLK 148     // 1 block per SM
#define NTHR 512

typedef unsigned long long ull;

// persistent state / scratch (device globals; no allocation)
__device__ float g_c[Bsz*Hd];
__device__ float g_hmem[Bsz*Md*Rd];
__device__ float g_hent[Bsz*Rd];
__device__ int   g_sel[Bsz];
__device__ float g_fcwxT[Xd*Md];       // fc_w x-part transposed (k-major)
__device__ float g_wcomb[Hd*256];      // [k][0:128]=fc_w c-part^T, [k][128:256]=trans_w^T
__device__ float g_xh[Td*Bsz*Md];      // precomputed x-part of head (NO fc_b; added in T2)
__device__ float g_cc2s[Bsz*NG1];      // scaled [c|hent] part of concat
__device__ float g_g1p[14][Bsz*NG1];   // gates1 K-chunk partials
__device__ float g_prep[4][Bsz*NPRE];  // big GEMM K-chunk partials
__device__ float g_tp[32][Bsz*256];    // tail GEMM K-chunk partials

// grid barrier state (replay-safe: every barrier leaves arrive=0, gen+1)
__device__ unsigned g_bar_arrive;
__device__ volatile unsigned g_bar_gen;

__device__ __forceinline__ float sigf(float v){ return 1.0f/(1.0f+expf(-v)); }
__device__ __forceinline__ ull pack2(float v){ ull r; asm("mov.b64 %0, {%1, %1};" : "=l"(r) : "f"(v)); return r; }
__device__ __forceinline__ void ffma2(ull &d, ull a, ull b){ asm("fma.rn.f32x2 %0, %1, %2, %0;" : "+l"(d) : "l"(a), "l"(b)); }
__device__ __forceinline__ float2 unpk(ull v){ float2 f; asm("mov.b64 {%0, %1}, %2;" : "=f"(f.x), "=f"(f.y) : "l"(v)); return f; }
__device__ __forceinline__ float4 ld4(const float* p){ return *(const float4*)p; }

__device__ __forceinline__ void gridbar()
{
    __threadfence();
    __syncthreads();
    if (threadIdx.x == 0){
        unsigned gen = g_bar_gen;
        if (atomicAdd(&g_bar_arrive, 1u) == NBLK-1u){
            g_bar_arrive = 0u;
            __threadfence();
            g_bar_gen = gen + 1u;
        } else {
            while (g_bar_gen == gen) { }
            __threadfence();
        }
    }
    __syncthreads();
}

// ============ unified 128x128 GEMM unit: 512 threads, 4x8 thread tile, FFMA2 =========
// A frag: 1 LDS.128 (broadcast-friendly); B frag split at [tn*4] and [64+tn*4]
// (16 lane addresses stride 16B -> all smem slots covered, conflict-free).

template<int MODE>
__device__ __forceinline__ float4 loadA(const float* __restrict__ x, int t, int row, int kg)
{
    if (MODE == 0){            // concat [x | c | hent]
        const float* p;
        if (kg < Xd)       p = x + ((size_t)t*Bsz + row)*Xd + kg;
        else if (kg < XHD) p = g_c + (size_t)row*Hd + (kg - Xd);
        else               p = g_hent + (size_t)row*Rd + (kg - XHD);
        return ld4(p);
    } else if (MODE == 1){     // [x | cc2s]
        const float* p = (kg < Xd) ? (x + ((size_t)t*Bsz + row)*Xd + kg)
                                   : (g_cc2s + (size_t)row*NG1 + (kg - Xd));
        return ld4(p);
    } else if (MODE == 2){     // g_c
        return ld4(g_c + (size_t)row*Hd + kg);
    } else {                   // MODE 3: x flat rows (row = global row in T*B)
        return ld4(x + (size_t)row*Xd + kg);
    }
}

template<int MODE>
__device__ void gemm128(float* SM, const float* __restrict__ x, int t,
                        const float* __restrict__ Bm, int ldb,
                        int rb, int nb, int kbase, int nkt,
                        float* __restrict__ outP, int ldo)
{
    float (*As)[16][132] = (float(*)[16][132])SM;
    float (*Bs)[16][128] = (float(*)[16][128])(SM + 2*16*132);
    const int tid = threadIdx.x;
    const int tm = tid >> 4;           // 0..31 -> rows tm*4..+3
    const int tn = tid & 15;           // col groups: tn*4 and 64+tn*4
    const int ar = tid >> 2, ak = (tid & 3)*4;   // A staging (128x16 = 512 float4)
    const int bk = tid >> 5, bc = (tid & 31)*4;  // B staging (16x128 = 512 float4)

    ull acc[4][4] = {};

    float4 pa = loadA<MODE>(x, t, rb+ar, kbase + ak);
    float4 pb = ld4(Bm + (size_t)(kbase + bk)*ldb + nb + bc);

    for (int kt = 0; kt < nkt; kt++){
        const int p = kt & 1;
        As[p][ak+0][ar]=pa.x; As[p][ak+1][ar]=pa.y; As[p][ak+2][ar]=pa.z; As[p][ak+3][ar]=pa.w;
        *(float4*)&Bs[p][bk][bc] = pb;
        __syncthreads();
        if (kt+1 < nkt){
            int k0 = kbase + (kt+1)*16;
            pa = loadA<MODE>(x, t, rb+ar, k0 + ak);
            pb = ld4(Bm + (size_t)(k0 + bk)*ldb + nb + bc);
        }
        #pragma unroll
        for (int kk = 0; kk < 16; kk++){
            float4 a = *(const float4*)&As[p][kk][tm*4];
            ulonglong2 b0 = *(const ulonglong2*)&Bs[p][kk][tn*4];
            ulonglong2 b1 = *(const ulonglong2*)&Bs[p][kk][64 + tn*4];
            float av[4] = {a.x, a.y, a.z, a.w};
            #pragma unroll
            for (int r = 0; r < 4; r++){
                ull ap = pack2(av[r]);
                ffma2(acc[r][0], ap, b0.x);
                ffma2(acc[r][1], ap, b0.y);
                ffma2(acc[r][2], ap, b1.x);
                ffma2(acc[r][3], ap, b1.y);
            }
        }
        __syncthreads();
    }
    #pragma unroll
    for (int r = 0; r < 4; r++){
        float2 c0 = unpk(acc[r][0]), c1 = unpk(acc[r][1]);
        float2 c2 = unpk(acc[r][2]), c3 = unpk(acc[r][3]);
        float* op = outP + (size_t)(rb + tm*4 + r)*ldo + nb + tn*4;
        float4 o0 = {c0.x, c0.y, c1.x, c1.y};
        float4 o1 = {c2.x, c2.y, c3.x, c3.y};
        *(float4*)op = o0;
        *(float4*)(op + 64) = o1;
    }
}

// =========================== prologue phases =========================================

__device__ void phInit(const float* __restrict__ fc_w, const float* __restrict__ trans_w,
                       const float* __restrict__ c_bias, const float* __restrict__ hmem_bias,
                       int bid, int tid)
{
    for (int idx = bid*NTHR + tid; idx < Bsz*Md*Rd; idx += NBLK*NTHR)
        g_hmem[idx] = hmem_bias[idx & (Md*Rd-1)];
    for (int idx = bid*NTHR + tid; idx < Bsz*Hd; idx += NBLK*NTHR)
        g_c[idx] = tanhf(c_bias[idx & (Hd-1)]);
    for (int idx = bid*NTHR + tid; idx < Xd*Md; idx += NBLK*NTHR){
        int k = idx >> 7, m = idx & 127;
        g_fcwxT[idx] = fc_w[m*XHD + k];
    }
    for (int idx = bid*NTHR + tid; idx < Hd*256; idx += NBLK*NTHR){
        int k = idx >> 8, c = idx & 255;
        g_wcomb[idx] = (c < 128) ? fc_w[c*XHD + Xd + k] : trans_w[(c-128)*Hd + k];
    }
}

// Xh = x(T*B,256) @ fcwxT(256,128): 512 row-tiles of 128, K=256 (16 kt), MODE 3
__device__ void phXhead(float* SM, const float* __restrict__ x, int bid)
{
    for (int u = bid; u < (Td*Bsz)/128; u += NBLK)
        gemm128<3>(SM, x, 0, g_fcwxT, Md, u*128, 0, 0, 16, g_xh, Md);
}

// =========================== per-step phases =========================================

// G1: gates1 partials. 140 units = 10 tiles (128x128) x 14 K-chunks (K64, 4 kt).
__device__ void phG1(float* SM, const float* __restrict__ x,
                     const float* __restrict__ W1, int t, int bid)
{
    if (bid >= 140) return;
    const int tile = bid % 10, z = bid / 10;
    const int rb = (tile / 5) * 128, nb = (tile % 5) * 128;
    gemm128<0>(SM, x, t, W1, NG1, rb, nb, z*64, 4, g_g1p[z], NG1);
}

// G2: combine 14 partials, sigmoid-scale [c|hent] -> g_cc2s
__device__ void phG2(const float* __restrict__ bias1, int bid, int tid)
{
    for (int idx = bid*NTHR + tid; idx < Bsz*160; idx += NBLK*NTHR){
        int row = idx / 160;
        int c = (idx - row*160) * 4;
        size_t o = (size_t)row*NG1 + c;
        float4 s = ld4(g_g1p[0] + o);
        #pragma unroll
        for (int z = 1; z < 14; z++){
            float4 p = ld4(g_g1p[z] + o);
            s.x += p.x; s.y += p.y; s.z += p.z; s.w += p.w;
        }
        float4 b = ld4(bias1 + c);
        float4 cv = (c < Hd) ? ld4(g_c + (size_t)row*Hd + c)
                             : ld4(g_hent + (size_t)row*Rd + (c - Hd));
        float4 r;
        r.x = cv.x * sigf(s.x + b.x);
        r.y = cv.y * sigf(s.y + b.y);
        r.z = cv.z * sigf(s.z + b.z);
        r.w = cv.w * sigf(s.w + b.w);
        *(float4*)(g_cc2s + o) = r;
    }
}

// Big: 136 units = 34 tiles (128x128) x 4 K-chunks (K224, 14 kt).
__device__ void phBig(float* SM, const float* __restrict__ x,
                      const float* __restrict__ Wf, int t, int bid)
{
    if (bid >= 136) return;
    const int tile = bid % 34, z = bid / 34;
    const int rb = (tile / 17) * 128, nb = (tile % 17) * 128;
    gemm128<1>(SM, x, t, Wf, NPRE, rb, nb, z*224, 14, g_prep[z], NPRE);
}

// C: combine 4 big partials + LSTM / r epilogue -> g_c, out
__device__ void phC(const float* __restrict__ bias, float* __restrict__ out,
                    int t, int bid, int tid)
{
    for (int idx = bid*NTHR + tid; idx < Bsz*Hd; idx += NBLK*NTHR){
        int row = idx >> 9, n = idx & 511;
        size_t base = (size_t)row*NPRE + n;
        float pi = 0.f, pj = 0.f, pf = 0.f, po = 0.f;
        #pragma unroll
        for (int z = 0; z < 4; z++){
            pi += g_prep[z][base];
            pj += g_prep[z][base+512];
            pf += g_prep[z][base+1024];
            po += g_prep[z][base+1536];
        }
        pi += bias[n]; pj += bias[512+n]; pf += bias[1024+n]; po += bias[1536+n];
        float c_old = g_c[row*Hd + n];
        float nc = tanhf(c_old*sigf(pf + 1.0f) + sigf(pi)*tanhf(pj));
        g_c[row*Hd + n] = nc;
        out[(size_t)t*Bsz*ODIM + (size_t)row*ODIM + n] = nc * sigf(po);
    }
    for (int idx = bid*NTHR + tid; idx < Bsz*Md; idx += NBLK*NTHR){
        int row = idx >> 7, m = idx & 127;
        size_t base = (size_t)row*NPRE + 2048 + m;
        float s = 0.f;
        #pragma unroll
        for (int z = 0; z < 4; z++) s += g_prep[z][base];
        float rv = g_hent[row*Rd + m] * sigf(s + bias[2048 + m]);
        out[(size_t)t*Bsz*ODIM + (size_t)row*ODIM + Hd + m] = rv;
    }
}

// T1: tail GEMM partials. 128 units = 4 tiles (128x128) x 32 K-chunks (K16, 1 kt).
__device__ void phT1(float* SM, int bid)
{
    if (bid >= 128) return;
    const int tile = bid % 4, z = bid / 4;
    const int rb = (tile >> 1) * 128, nb = (tile & 1) * 128;
    gemm128<2>(SM, (const float*)0, 0, g_wcomb, 256, rb, nb, z*16, 1, g_tp[z], 256);
}

// T2: combine 32 partials (+fc_b/xh or trans_b) + gumbel/argmax + hmem scatter/gather
__device__ void phT2(float* SM, int* SI, const float* __restrict__ noise,
                     const float* __restrict__ fc_b, const float* __restrict__ trans_b,
                     int t, int bid, int tid)
{
    if (bid >= 64) return;
    float (*s_head)[132] = (float(*)[132])SM;
    float (*s_wv)[132]   = (float(*)[132])(SM + 4*132);
    int* s_sel = SI; int* s_selold = SI + 4;
    const int warp = tid >> 5, lane = tid & 31;
    const int b0 = bid * 4;
    const int tn = t + 1;

    if (tid < 4) s_selold[tid] = g_sel[b0 + tid];
    if (tid < 256){
        const int rg = tid >> 6;
        const int c4 = (tid & 63) * 4;
        size_t off = (size_t)(b0 + rg)*256 + c4;
        float4 a = {0.f,0.f,0.f,0.f};
        #pragma unroll
        for (int z = 0; z < 32; z++){
            float4 p = ld4(g_tp[z] + off);
            a.x += p.x; a.y += p.y; a.z += p.z; a.w += p.w;
        }
        if (c4 < 128){
            float4 xh = ld4(g_xh + ((size_t)tn*Bsz + b0 + rg)*Md + c4);
            float4 fb = ld4(fc_b + c4);
            a.x += xh.x + fb.x; a.y += xh.y + fb.y;
            a.z += xh.z + fb.z; a.w += xh.w + fb.w;
            *(float4*)&s_head[rg][c4] = a;
        } else {
            float4 tb = ld4(trans_b + (c4 - 128));
            a.x += tb.x; a.y += tb.y; a.z += tb.z; a.w += tb.w;
            *(float4*)&s_wv[rg][c4 - 128] = a;
        }
    }
    __syncthreads();

    if (warp < 4){
        int r = warp;
        float4 hv = *(const float4*)&s_head[r][lane*4];
        float4 nz = ld4(noise + ((size_t)tn*Bsz + b0 + r)*Md + lane*4);
        float v[4];
        v[0] = hv.x - logf(1e-20f - logf(1e-20f + nz.x));
        v[1] = hv.y - logf(1e-20f - logf(1e-20f + nz.y));
        v[2] = hv.z - logf(1e-20f - logf(1e-20f + nz.z));
        v[3] = hv.w - logf(1e-20f - logf(1e-20f + nz.w));
        float best = v[0]; int bi = lane*4;
        #pragma unroll
        for (int c = 1; c < 4; c++) if (v[c] > best){ best = v[c]; bi = lane*4 + c; }
        #pragma unroll
        for (int off = 16; off; off >>= 1){
            float ov = __shfl_xor_sync(0xffffffffu, best, off);
            int   oi = __shfl_xor_sync(0xffffffffu, bi,   off);
            if (ov > best || (ov == best && oi < bi)){ best = ov; bi = oi; }
        }
        if (lane == 0) s_sel[r] = bi;
    } else if (warp < 8 && t >= 0){
        int r = warp - 4;
        float4 wv = *(const float4*)&s_wv[r][lane*4];
        int idx = (t < Md) ? t : s_selold[r];
        *(float4*)(g_hmem + ((size_t)(b0+r)*Md + idx)*Rd + lane*4) = wv;
    }
    __syncthreads();

    if (warp < 4){
        int r = warp;
        int sel = s_sel[r];
        float4 h4 = ld4(g_hmem + ((size_t)(b0+r)*Md + sel)*Rd + lane*4);
        *(float4*)(g_hent + (size_t)(b0+r)*Rd + lane*4) = h4;
        if (lane == 0) g_sel[b0+r] = sel;
    }
}

// ---------------- persistent kernel: prologue + whole scan ----------------
__global__ __launch_bounds__(NTHR, 1) void k_persist(
    const float* __restrict__ x, const float* __restrict__ noise,
    const float* __restrict__ Wf, const float* __restrict__ bias,
    const float* __restrict__ W1, const float* __restrict__ bias1,
    const float* __restrict__ fc_w, const float* __restrict__ fc_b,
    const float* __restrict__ trans_w, const float* __restrict__ trans_b,
    const float* __restrict__ c_bias, const float* __restrict__ hmem_b,
    float* __restrict__ out)
{
    __shared__ __align__(16) float SM[8320];   // As[2][16][132] + Bs[2][16][128]
    __shared__ int SI[8];
    const int tid = threadIdx.x, bid = blockIdx.x;

    // prologue
    phInit(fc_w, trans_w, c_bias, hmem_b, bid, tid);      gridbar();
    phXhead(SM, x, bid);                                  gridbar();
    phT1(SM, bid);                                        gridbar();
    phT2(SM, SI, noise, fc_b, trans_b, -1, bid, tid);     gridbar();

    for (int t = 0; t < Td; t++){
        phG1(SM, x, W1, t, bid);                          gridbar();
        phG2(bias1, bid, tid);                            gridbar();
        phBig(SM, x, Wf, t, bid);                         gridbar();
        phC(bias, out, t, bid, tid);                      gridbar();
        if (t < Td - 1){
            phT1(SM, bid);                                gridbar();
            phT2(SM, SI, noise, fc_b, trans_b, t, bid, tid); gridbar();
        }
    }
}

extern "C" void kernel_launch(void* const* d_in, const int* in_sizes, int n_in,
                              void* d_out, int out_size)
{
    const float* x       = (const float*)d_in[0];
    const float* noise   = (const float*)d_in[1];
    const float* W_full  = (const float*)d_in[2];
    const float* bias    = (const float*)d_in[3];
    const float* W_full1 = (const float*)d_in[4];
    const float* bias1   = (const float*)d_in[5];
    const float* fc_w    = (const float*)d_in[6];
    const float* fc_b    = (const float*)d_in[7];
    const float* trans_w = (const float*)d_in[8];
    const float* trans_b = (const float*)d_in[9];
    const float* c_bias  = (const float*)d_in[10];
    const float* hmem_b  = (const float*)d_in[11];
    float* out = (float*)d_out;

    k_persist<<<NBLK, NTHR>>>(x, noise, W_full, bias, W_full1, bias1,
                              fc_w, fc_b, trans_w, trans_b, c_bias, hmem_b, out);
}